// round 2
// baseline (speedup 1.0000x reference)
#include <cuda_runtime.h>

#define NN 100000
#define NE 625000
#define DD 128
#define NB_SCAN 98   // ceil(NN/1024)

// ---------------- device scratch (static, allowed) ----------------
__device__ int   g_is64;
__device__ int   g_deg[NN];
__device__ int   g_off[NN];
__device__ int   g_cur[NN];
__device__ int   g_bsum[NB_SCAN];
__device__ int   g_csr[NE];
__device__ float g_agg[(size_t)NN * DD];   // aggregated features (reused both layers)
__device__ float g_h[(size_t)NN * DD];     // layer-1 hidden
__device__ float g_wcat1[2 * DD * DD];     // [256][128]: k<128 -> W1_l^T, k>=128 -> W1_r^T
__device__ float g_wcat2[2 * DD * DD];

// ---------------- dtype detection: int64 vs int32 edge_index ----------------
// int64 little-endian indices < 2^31 -> every odd 32-bit word is 0.
__global__ void k_detect(const int* __restrict__ w) {
    if (threadIdx.x == 0 && blockIdx.x == 0) {
        int is64 = 1;
        for (int i = 0; i < 512; i++)
            if (w[2 * i + 1] != 0) { is64 = 0; break; }
        g_is64 = is64;
    }
}

__device__ __forceinline__ int edge_at(const void* ei, int idx) {
    if (g_is64) return (int)((const long long*)ei)[idx];
    return ((const int*)ei)[idx];
}

// ---------------- CSR build ----------------
__global__ void k_zero() {
    int i = blockIdx.x * blockDim.x + threadIdx.x;
    if (i < NN) { g_deg[i] = 0; g_cur[i] = 0; }
}

__global__ void k_count(const void* __restrict__ ei) {
    int e = blockIdx.x * blockDim.x + threadIdx.x;
    if (e < NE) atomicAdd(&g_deg[edge_at(ei, NE + e)], 1);   // dst row
}

__global__ void k_scan1() {
    __shared__ int s[1024];
    int tid = threadIdx.x;
    int gid = blockIdx.x * 1024 + tid;
    int v = (gid < NN) ? g_deg[gid] : 0;
    s[tid] = v;
    __syncthreads();
    for (int o = 1; o < 1024; o <<= 1) {
        int t = (tid >= o) ? s[tid - o] : 0;
        __syncthreads();
        s[tid] += t;
        __syncthreads();
    }
    if (gid < NN) g_off[gid] = s[tid] - v;          // exclusive
    if (tid == 1023) g_bsum[blockIdx.x] = s[tid];   // block total
}

__global__ void k_scan2() {
    __shared__ int s[128];
    int tid = threadIdx.x;
    int v = (tid < NB_SCAN) ? g_bsum[tid] : 0;
    s[tid] = v;
    __syncthreads();
    for (int o = 1; o < 128; o <<= 1) {
        int t = (tid >= o) ? s[tid - o] : 0;
        __syncthreads();
        s[tid] += t;
        __syncthreads();
    }
    if (tid < NB_SCAN) g_bsum[tid] = s[tid] - v;    // exclusive block offsets
}

__global__ void k_scan3() {
    int gid = blockIdx.x * 1024 + threadIdx.x;
    if (gid < NN) g_off[gid] += g_bsum[blockIdx.x];
}

__global__ void k_scatter(const void* __restrict__ ei) {
    int e = blockIdx.x * blockDim.x + threadIdx.x;
    if (e < NE) {
        int d = edge_at(ei, NE + e);                 // dst
        int pos = g_off[d] + atomicAdd(&g_cur[d], 1);
        g_csr[pos] = edge_at(ei, e);                 // src
    }
}

// ---------------- weight concat/transpose: Wcat[k][o] ----------------
__global__ void k_wcat(const float* __restrict__ Wl1, const float* __restrict__ Wr1,
                       const float* __restrict__ Wl2, const float* __restrict__ Wr2) {
    int idx = blockIdx.x * blockDim.x + threadIdx.x;   // 0 .. 4*DD*DD-1
    int which = idx >= 2 * DD * DD;
    int i = idx & (2 * DD * DD - 1);
    int k = i >> 7, o = i & 127;
    const float* Wl = which ? Wl2 : Wl1;
    const float* Wr = which ? Wr2 : Wr1;
    float v = (k < DD) ? Wl[o * DD + k] : Wr[o * DD + (k - DD)];
    (which ? g_wcat2 : g_wcat1)[i] = v;
}

// ---------------- mean aggregation: one warp per node, float4 lanes ----------------
__global__ void k_agg(const float* __restrict__ X, float* __restrict__ out) {
    int warp = (blockIdx.x * blockDim.x + threadIdx.x) >> 5;
    if (warp >= NN) return;
    int lane = threadIdx.x & 31;
    int beg = g_off[warp];
    int d = g_deg[warp];
    const float4* Xv = (const float4*)X;
    float4 acc = make_float4(0.f, 0.f, 0.f, 0.f);
    int j = 0;
    for (; j + 1 < d; j += 2) {   // 2-way MLP
        int s0 = __ldg(&g_csr[beg + j]);
        int s1 = __ldg(&g_csr[beg + j + 1]);
        float4 v0 = __ldg(&Xv[(size_t)s0 * 32 + lane]);
        float4 v1 = __ldg(&Xv[(size_t)s1 * 32 + lane]);
        acc.x += v0.x + v1.x; acc.y += v0.y + v1.y;
        acc.z += v0.z + v1.z; acc.w += v0.w + v1.w;
    }
    if (j < d) {
        int s0 = __ldg(&g_csr[beg + j]);
        float4 v0 = __ldg(&Xv[(size_t)s0 * 32 + lane]);
        acc.x += v0.x; acc.y += v0.y; acc.z += v0.z; acc.w += v0.w;
    }
    float inv = (d > 0) ? (1.0f / (float)d) : 0.0f;
    acc.x *= inv; acc.y *= inv; acc.z *= inv; acc.w *= inv;
    ((float4*)out)[(size_t)warp * 32 + lane] = acc;
}

// ---------------- fused dual GEMM: C = A1@Wl^T + A2@Wr^T + b (opt ReLU) ----------------
// C[i][o] = sum_{k<256} Acat[i][k] * Wcat[k][o],
//   Acat[i][k] = k<128 ? A1[i][k] : A2[i][k-128]
// Block: 128 rows x 128 cols, 256 threads, 8x8 per-thread tile, BK=16.
__global__ __launch_bounds__(256, 2)
void k_gemm(const float* __restrict__ A1, const float* __restrict__ A2,
            const float* __restrict__ W, const float* __restrict__ bias,
            float* __restrict__ C, int n, int doRelu)
{
    __shared__ float As[16][128];   // [k][row]
    __shared__ float Bs[16][128];   // [k][col]
    const int tid = threadIdx.x;
    const int row0 = blockIdx.x * 128;
    const int tx = tid & 15;        // col group (8 cols)
    const int ty = tid >> 4;        // row group (8 rows)

    const int aRow = tid >> 1;              // 0..127
    const int aK   = (tid & 1) * 8;         // 0 or 8
    const int bRow = tid >> 4;              // 0..15 (k within tile)
    const int bCol = (tid & 15) * 8;        // 0..120

    float acc[8][8];
#pragma unroll
    for (int i = 0; i < 8; i++)
#pragma unroll
        for (int jj = 0; jj < 8; jj++) acc[i][jj] = 0.f;

    const int r = row0 + aRow;
    const bool rOK = (r < n);

    for (int k0 = 0; k0 < 256; k0 += 16) {
        const float* Asrc = (k0 < 128) ? A1 : A2;
        float4 a0 = make_float4(0.f, 0.f, 0.f, 0.f), a1 = a0;
        if (rOK) {
            const float* p = Asrc + (size_t)r * DD + (k0 & 127) + aK;
            a0 = *(const float4*)p;
            a1 = *(const float4*)(p + 4);
        }
        const float* bp = W + (k0 + bRow) * DD + bCol;
        float4 b0 = *(const float4*)bp;
        float4 b1 = *(const float4*)(bp + 4);

        __syncthreads();   // protect previous-iter smem reads
        As[aK + 0][aRow] = a0.x; As[aK + 1][aRow] = a0.y;
        As[aK + 2][aRow] = a0.z; As[aK + 3][aRow] = a0.w;
        As[aK + 4][aRow] = a1.x; As[aK + 5][aRow] = a1.y;
        As[aK + 6][aRow] = a1.z; As[aK + 7][aRow] = a1.w;
        *(float4*)&Bs[bRow][bCol]     = b0;
        *(float4*)&Bs[bRow][bCol + 4] = b1;
        __syncthreads();

#pragma unroll
        for (int kk = 0; kk < 16; kk++) {
            float a[8], b[8];
            *(float4*)(a)     = *(const float4*)&As[kk][ty * 8];
            *(float4*)(a + 4) = *(const float4*)&As[kk][ty * 8 + 4];
            *(float4*)(b)     = *(const float4*)&Bs[kk][tx * 8];
            *(float4*)(b + 4) = *(const float4*)&Bs[kk][tx * 8 + 4];
#pragma unroll
            for (int i = 0; i < 8; i++)
#pragma unroll
                for (int jj = 0; jj < 8; jj++)
                    acc[i][jj] = fmaf(a[i], b[jj], acc[i][jj]);
        }
    }

    float bb[8];
#pragma unroll
    for (int jj = 0; jj < 8; jj++) bb[jj] = __ldg(&bias[tx * 8 + jj]);

#pragma unroll
    for (int i = 0; i < 8; i++) {
        int rr = row0 + ty * 8 + i;
        if (rr < n) {
            float4 o0, o1;
            o0.x = acc[i][0] + bb[0]; o0.y = acc[i][1] + bb[1];
            o0.z = acc[i][2] + bb[2]; o0.w = acc[i][3] + bb[3];
            o1.x = acc[i][4] + bb[4]; o1.y = acc[i][5] + bb[5];
            o1.z = acc[i][6] + bb[6]; o1.w = acc[i][7] + bb[7];
            if (doRelu) {
                o0.x = fmaxf(o0.x, 0.f); o0.y = fmaxf(o0.y, 0.f);
                o0.z = fmaxf(o0.z, 0.f); o0.w = fmaxf(o0.w, 0.f);
                o1.x = fmaxf(o1.x, 0.f); o1.y = fmaxf(o1.y, 0.f);
                o1.z = fmaxf(o1.z, 0.f); o1.w = fmaxf(o1.w, 0.f);
            }
            float* cp = C + (size_t)rr * DD + tx * 8;
            *(float4*)cp       = o0;
            *(float4*)(cp + 4) = o1;
        }
    }
}

// ---------------- launch ----------------
extern "C" void kernel_launch(void* const* d_in, const int* in_sizes, int n_in,
                              void* d_out, int out_size) {
    const float* x   = (const float*)d_in[0];
    const void*  ei  = d_in[1];                 // int32 or int64, detected on device
    const float* W1l = (const float*)d_in[2];
    const float* b1  = (const float*)d_in[3];
    const float* W1r = (const float*)d_in[4];
    const float* W2l = (const float*)d_in[5];
    const float* b2  = (const float*)d_in[6];
    const float* W2r = (const float*)d_in[7];
    float* out = (float*)d_out;

    void* p;
    cudaGetSymbolAddress(&p, g_agg);   float* agg = (float*)p;
    cudaGetSymbolAddress(&p, g_h);     float* h   = (float*)p;
    cudaGetSymbolAddress(&p, g_wcat1); float* wc1 = (float*)p;
    cudaGetSymbolAddress(&p, g_wcat2); float* wc2 = (float*)p;

    // dtype detect + CSR build (once, reused by both layers)
    k_detect<<<1, 32>>>((const int*)ei);
    k_zero<<<(NN + 255) / 256, 256>>>();
    k_count<<<(NE + 255) / 256, 256>>>(ei);
    k_scan1<<<NB_SCAN, 1024>>>();
    k_scan2<<<1, 128>>>();
    k_scan3<<<NB_SCAN, 1024>>>();
    k_scatter<<<(NE + 255) / 256, 256>>>(ei);
    k_wcat<<<(4 * DD * DD) / 256, 256>>>(W1l, W1r, W2l, W2r);

    // Layer 1
    k_agg<<<(NN + 7) / 8, 256>>>(x, agg);
    k_gemm<<<(NN + 127) / 128, 256>>>(agg, x, wc1, b1, h, NN, 1);

    // Layer 2
    k_agg<<<(NN + 7) / 8, 256>>>(h, agg);
    k_gemm<<<(NN + 127) / 128, 256>>>(agg, h, wc2, b2, out, NN, 0);
}

// round 3
// speedup vs baseline: 1.7922x; 1.7922x over previous
#include <cuda_runtime.h>

#define NN 100000
#define NE 625000
#define DD 128
#define NB_SCAN 98   // ceil(NN/1024)

// ---------------- device scratch (static, allowed) ----------------
__device__ int   g_is64;
__device__ int   g_deg[NN];
__device__ int   g_off[NN];
__device__ int   g_cur[NN];
__device__ int   g_bsum[NB_SCAN];
__device__ int   g_csr[NE];
__device__ float g_agg[(size_t)NN * DD];   // aggregated features (reused both layers)
__device__ float g_h[(size_t)NN * DD];     // layer-1 hidden
__device__ float g_wcat1[2 * DD * DD];     // [256][128]: k<128 -> W1_l^T, k>=128 -> W1_r^T
__device__ float g_wcat2[2 * DD * DD];

// ---------------- dtype detection: int64 vs int32 edge_index ----------------
// int64 little-endian indices < 2^31 -> every odd 32-bit word is 0.
__global__ void k_detect(const int* __restrict__ w) {
    int lane = threadIdx.x;
    int nz = 0;
    if (w[2 * lane + 1] != 0) nz = 1;
    if (w[2 * (lane + 32) + 1] != 0) nz = 1;
    unsigned m = __ballot_sync(0xFFFFFFFF, nz);
    if (lane == 0) g_is64 = (m == 0u) ? 1 : 0;
}

__device__ __forceinline__ int edge_at(const void* ei, int idx) {
    if (g_is64) return (int)((const long long*)ei)[idx];
    return ((const int*)ei)[idx];
}

// ---------------- CSR build ----------------
__global__ void k_zero() {
    int i = blockIdx.x * blockDim.x + threadIdx.x;
    if (i < NN) { g_deg[i] = 0; g_cur[i] = 0; }
}

__global__ void k_count(const void* __restrict__ ei) {
    int e = blockIdx.x * blockDim.x + threadIdx.x;
    if (e < NE) atomicAdd(&g_deg[edge_at(ei, NE + e)], 1);   // dst row
}

__global__ void k_scan1() {
    __shared__ int s[1024];
    int tid = threadIdx.x;
    int gid = blockIdx.x * 1024 + tid;
    int v = (gid < NN) ? g_deg[gid] : 0;
    s[tid] = v;
    __syncthreads();
    for (int o = 1; o < 1024; o <<= 1) {
        int t = (tid >= o) ? s[tid - o] : 0;
        __syncthreads();
        s[tid] += t;
        __syncthreads();
    }
    if (gid < NN) g_off[gid] = s[tid] - v;          // exclusive
    if (tid == 1023) g_bsum[blockIdx.x] = s[tid];   // block total
}

__global__ void k_scan2() {
    __shared__ int s[128];
    int tid = threadIdx.x;
    int v = (tid < NB_SCAN) ? g_bsum[tid] : 0;
    s[tid] = v;
    __syncthreads();
    for (int o = 1; o < 128; o <<= 1) {
        int t = (tid >= o) ? s[tid - o] : 0;
        __syncthreads();
        s[tid] += t;
        __syncthreads();
    }
    if (tid < NB_SCAN) g_bsum[tid] = s[tid] - v;    // exclusive block offsets
}

__global__ void k_scan3() {
    int gid = blockIdx.x * 1024 + threadIdx.x;
    if (gid < NN) g_off[gid] += g_bsum[blockIdx.x];
}

__global__ void k_scatter(const void* __restrict__ ei) {
    int e = blockIdx.x * blockDim.x + threadIdx.x;
    if (e < NE) {
        int d = edge_at(ei, NE + e);                 // dst
        int pos = g_off[d] + atomicAdd(&g_cur[d], 1);
        g_csr[pos] = edge_at(ei, e);                 // src
    }
}

// ---------------- weight concat/transpose: Wcat[k][o] ----------------
__global__ void k_wcat(const float* __restrict__ Wl1, const float* __restrict__ Wr1,
                       const float* __restrict__ Wl2, const float* __restrict__ Wr2) {
    int idx = blockIdx.x * blockDim.x + threadIdx.x;   // 0 .. 4*DD*DD-1
    int which = idx >= 2 * DD * DD;
    int i = idx & (2 * DD * DD - 1);
    int k = i >> 7, o = i & 127;
    const float* Wl = which ? Wl2 : Wl1;
    const float* Wr = which ? Wr2 : Wr1;
    float v = (k < DD) ? Wl[o * DD + k] : Wr[o * DD + (k - DD)];
    (which ? g_wcat2 : g_wcat1)[i] = v;
}

// ---------------- mean aggregation: one warp per node, float4 lanes ----------------
__global__ void k_agg(const float* __restrict__ X, float* __restrict__ out) {
    int warp = (blockIdx.x * blockDim.x + threadIdx.x) >> 5;
    if (warp >= NN) return;
    int lane = threadIdx.x & 31;
    int beg = g_off[warp];
    int d = g_deg[warp];
    const float4* Xv = (const float4*)X;
    float4 acc = make_float4(0.f, 0.f, 0.f, 0.f);
    int j = 0;
    for (; j + 1 < d; j += 2) {   // 2-way MLP
        int s0 = __ldg(&g_csr[beg + j]);
        int s1 = __ldg(&g_csr[beg + j + 1]);
        float4 v0 = __ldg(&Xv[(size_t)s0 * 32 + lane]);
        float4 v1 = __ldg(&Xv[(size_t)s1 * 32 + lane]);
        acc.x += v0.x + v1.x; acc.y += v0.y + v1.y;
        acc.z += v0.z + v1.z; acc.w += v0.w + v1.w;
    }
    if (j < d) {
        int s0 = __ldg(&g_csr[beg + j]);
        float4 v0 = __ldg(&Xv[(size_t)s0 * 32 + lane]);
        acc.x += v0.x; acc.y += v0.y; acc.z += v0.z; acc.w += v0.w;
    }
    float inv = (d > 0) ? (1.0f / (float)d) : 0.0f;
    acc.x *= inv; acc.y *= inv; acc.z *= inv; acc.w *= inv;
    ((float4*)out)[(size_t)warp * 32 + lane] = acc;
}

// ---------------- tf32 tensor-core fused dual GEMM ----------------
// C[i][o] = sum_{k<256} Acat[i][k] * Wcat[k][o] + bias[o]  (opt ReLU)
//   Acat[i][k] = k<128 ? A1[i][k] : A2[i][k-128]
// Block 128x128, 8 warps (4x2), warp tile 32x64 = 2x8 m16n8k8 frags, BK=16.
__device__ __forceinline__ unsigned f2tf(float f) {
    unsigned u;
    asm("cvt.rna.tf32.f32 %0, %1;" : "=r"(u) : "f"(f));
    return u;
}

__global__ __launch_bounds__(256, 2)
void k_gemm(const float* __restrict__ A1, const float* __restrict__ A2,
            const float* __restrict__ W, const float* __restrict__ bias,
            float* __restrict__ C, int n, int doRelu)
{
    __shared__ unsigned As[128][20];   // [row][k]  pad 20 -> conflict-free frag loads
    __shared__ unsigned Bs[16][136];   // [k][col]  pad 136 -> conflict-free frag loads

    const int tid  = threadIdx.x;
    const int lane = tid & 31;
    const int warp = tid >> 5;
    const int warpM = warp & 3;        // 4 warp-rows of 32
    const int warpN = warp >> 2;       // 2 warp-cols of 64
    const int rowBase = warpM * 32;
    const int colBase = warpN * 64;
    const int row0 = blockIdx.x * 128;

    const int qid = lane >> 2;         // 0..7
    const int rid = lane & 3;          // 0..3

    float c[2][8][4];
#pragma unroll
    for (int mi = 0; mi < 2; mi++)
#pragma unroll
        for (int ni = 0; ni < 8; ni++)
#pragma unroll
            for (int t = 0; t < 4; t++) c[mi][ni][t] = 0.f;

    const int aRow = tid >> 1;             // 0..127
    const int aK   = (tid & 1) * 8;        // 0 or 8
    const int bK   = tid >> 4;             // 0..15
    const int bCol = (tid & 15) * 8;       // 0..120
    const int r = row0 + aRow;
    const bool rOK = (r < n);

    for (int k0 = 0; k0 < 256; k0 += 16) {
        const float* Asrc = (k0 < 128) ? A1 : A2;
        float4 a0 = make_float4(0.f, 0.f, 0.f, 0.f), a1 = a0;
        if (rOK) {
            const float* p = Asrc + (size_t)r * DD + (k0 & 127) + aK;
            a0 = *(const float4*)p;
            a1 = *(const float4*)(p + 4);
        }
        const float* bp = W + (k0 + bK) * DD + bCol;
        float4 b0 = *(const float4*)bp;
        float4 b1 = *(const float4*)(bp + 4);

        __syncthreads();   // protect previous-iter smem reads
        {
            uint4 u;
            u.x = f2tf(a0.x); u.y = f2tf(a0.y); u.z = f2tf(a0.z); u.w = f2tf(a0.w);
            *(uint4*)&As[aRow][aK] = u;
            u.x = f2tf(a1.x); u.y = f2tf(a1.y); u.z = f2tf(a1.z); u.w = f2tf(a1.w);
            *(uint4*)&As[aRow][aK + 4] = u;
            u.x = f2tf(b0.x); u.y = f2tf(b0.y); u.z = f2tf(b0.z); u.w = f2tf(b0.w);
            *(uint4*)&Bs[bK][bCol] = u;
            u.x = f2tf(b1.x); u.y = f2tf(b1.y); u.z = f2tf(b1.z); u.w = f2tf(b1.w);
            *(uint4*)&Bs[bK][bCol + 4] = u;
        }
        __syncthreads();

#pragma unroll
        for (int kk = 0; kk < 16; kk += 8) {
            unsigned af[2][4];
#pragma unroll
            for (int mi = 0; mi < 2; mi++) {
                const int rr = rowBase + mi * 16 + qid;
                const int kc = kk + rid;
                af[mi][0] = As[rr][kc];
                af[mi][1] = As[rr + 8][kc];
                af[mi][2] = As[rr][kc + 4];
                af[mi][3] = As[rr + 8][kc + 4];
            }
#pragma unroll
            for (int ni = 0; ni < 8; ni++) {
                const int col = colBase + ni * 8 + qid;
                const unsigned bf0 = Bs[kk + rid][col];
                const unsigned bf1 = Bs[kk + 4 + rid][col];
#pragma unroll
                for (int mi = 0; mi < 2; mi++) {
                    asm volatile(
                        "mma.sync.aligned.m16n8k8.row.col.f32.tf32.tf32.f32 "
                        "{%0,%1,%2,%3}, {%4,%5,%6,%7}, {%8,%9}, {%0,%1,%2,%3};\n"
                        : "+f"(c[mi][ni][0]), "+f"(c[mi][ni][1]),
                          "+f"(c[mi][ni][2]), "+f"(c[mi][ni][3])
                        : "r"(af[mi][0]), "r"(af[mi][1]),
                          "r"(af[mi][2]), "r"(af[mi][3]),
                          "r"(bf0), "r"(bf1));
                }
            }
        }
    }

    // epilogue: c0/c1 -> (row, col..col+1), c2/c3 -> (row+8, col..col+1)
#pragma unroll
    for (int mi = 0; mi < 2; mi++) {
#pragma unroll
        for (int ni = 0; ni < 8; ni++) {
            const int col = colBase + ni * 8 + 2 * rid;
            const float bv0 = __ldg(&bias[col]);
            const float bv1 = __ldg(&bias[col + 1]);
            const int rr0 = row0 + rowBase + mi * 16 + qid;
            if (rr0 < n) {
                float v0 = c[mi][ni][0] + bv0;
                float v1 = c[mi][ni][1] + bv1;
                if (doRelu) { v0 = fmaxf(v0, 0.f); v1 = fmaxf(v1, 0.f); }
                *(float2*)&C[(size_t)rr0 * DD + col] = make_float2(v0, v1);
            }
            const int rr1 = rr0 + 8;
            if (rr1 < n) {
                float v2 = c[mi][ni][2] + bv0;
                float v3 = c[mi][ni][3] + bv1;
                if (doRelu) { v2 = fmaxf(v2, 0.f); v3 = fmaxf(v3, 0.f); }
                *(float2*)&C[(size_t)rr1 * DD + col] = make_float2(v2, v3);
            }
        }
    }
}

// ---------------- launch ----------------
extern "C" void kernel_launch(void* const* d_in, const int* in_sizes, int n_in,
                              void* d_out, int out_size) {
    const float* x   = (const float*)d_in[0];
    const void*  ei  = d_in[1];                 // int32 or int64, detected on device
    const float* W1l = (const float*)d_in[2];
    const float* b1  = (const float*)d_in[3];
    const float* W1r = (const float*)d_in[4];
    const float* W2l = (const float*)d_in[5];
    const float* b2  = (const float*)d_in[6];
    const float* W2r = (const float*)d_in[7];
    float* out = (float*)d_out;

    void* p;
    cudaGetSymbolAddress(&p, g_agg);   float* agg = (float*)p;
    cudaGetSymbolAddress(&p, g_h);     float* h   = (float*)p;
    cudaGetSymbolAddress(&p, g_wcat1); float* wc1 = (float*)p;
    cudaGetSymbolAddress(&p, g_wcat2); float* wc2 = (float*)p;

    // dtype detect + CSR build (once, reused by both layers)
    k_detect<<<1, 32>>>((const int*)ei);
    k_zero<<<(NN + 255) / 256, 256>>>();
    k_count<<<(NE + 255) / 256, 256>>>(ei);
    k_scan1<<<NB_SCAN, 1024>>>();
    k_scan2<<<1, 128>>>();
    k_scan3<<<NB_SCAN, 1024>>>();
    k_scatter<<<(NE + 255) / 256, 256>>>(ei);
    k_wcat<<<(4 * DD * DD) / 256, 256>>>(W1l, W1r, W2l, W2r);

    // Layer 1
    k_agg<<<(NN + 7) / 8, 256>>>(x, agg);
    k_gemm<<<(NN + 127) / 128, 256>>>(agg, x, wc1, b1, h, NN, 1);

    // Layer 2
    k_agg<<<(NN + 7) / 8, 256>>>(h, agg);
    k_gemm<<<(NN + 127) / 128, 256>>>(agg, h, wc2, b2, out, NN, 0);
}

// round 4
// speedup vs baseline: 1.8220x; 1.0166x over previous
#include <cuda_runtime.h>

#define NN 100000
#define NE 625000
#define DD 128
#define NB 98   // ceil(NN/1024) — persistent CSR grid; must be <= resident capacity

// ---------------- device scratch (static, allowed) ----------------
__device__ int   g_is64;
__device__ int   g_bar_arrive;
__device__ int   g_bar_gen;
__device__ int   g_deg[NN];
__device__ int   g_off[NN];
__device__ int   g_cur[NN];
__device__ int   g_bsum[NB];
__device__ int   g_csr[NE];
__device__ float g_agg[(size_t)NN * DD];   // aggregated features (reused both layers)
__device__ float g_h[(size_t)NN * DD];     // layer-1 hidden
__device__ float g_wcat1[2 * DD * DD];     // [256][128]: k<128 -> W1_l^T, k>=128 -> W1_r^T
__device__ float g_wcat2[2 * DD * DD];

// ---------------- dtype detection + per-launch barrier reset ----------------
// int64 little-endian indices < 2^31 -> every odd 32-bit word is 0.
__global__ void k_detect(const int* __restrict__ w) {
    int lane = threadIdx.x;
    int nz = 0;
    if (w[2 * lane + 1] != 0) nz = 1;
    if (w[2 * (lane + 32) + 1] != 0) nz = 1;
    unsigned m = __ballot_sync(0xFFFFFFFF, nz);
    if (lane == 0) {
        g_is64 = (m == 0u) ? 1 : 0;
        g_bar_arrive = 0;
        g_bar_gen = 0;
    }
}

__device__ __forceinline__ int edge_at(const void* ei, int idx, int is64) {
    if (is64) return (int)((const long long*)ei)[idx];
    return ((const int*)ei)[idx];
}

// ---------------- software grid barrier (all NB blocks resident) ----------------
__device__ __forceinline__ void gridbar(int* gen) {
    __threadfence();
    __syncthreads();
    if (threadIdx.x == 0) {
        int my = *gen + 1;
        if (atomicAdd(&g_bar_arrive, 1) == NB - 1) {
            atomicExch(&g_bar_arrive, 0);
            __threadfence();
            atomicExch(&g_bar_gen, my);
        } else {
            while (atomicAdd(&g_bar_gen, 0) != my) { }
        }
        *gen = my;
    }
    __syncthreads();
}

// ---------------- fused CSR build + weight concat (one persistent kernel) ----------------
__global__ __launch_bounds__(1024)
void k_csr(const void* __restrict__ ei,
           const float* __restrict__ Wl1, const float* __restrict__ Wr1,
           const float* __restrict__ Wl2, const float* __restrict__ Wr2) {
    __shared__ int s[1024];
    const int tid = threadIdx.x;
    const int bid = blockIdx.x;
    const int gid = bid * 1024 + tid;
    const int is64 = g_is64;
    int gen = 0;

    // P0: zero counters + build Wcat (independent work folded in)
    if (gid < NN) { g_deg[gid] = 0; g_cur[gid] = 0; }
    if (gid < 4 * DD * DD) {
        int which = gid >> 15;                  // 0 or 1
        int i = gid & (2 * DD * DD - 1);
        int k = i >> 7, o = i & 127;
        const float* Wl = which ? Wl2 : Wl1;
        const float* Wr = which ? Wr2 : Wr1;
        float v = (k < DD) ? Wl[o * DD + k] : Wr[o * DD + (k - DD)];
        (which ? g_wcat2 : g_wcat1)[i] = v;
    }
    gridbar(&gen);

    // P1: degree count
    for (int e = gid; e < NE; e += NB * 1024)
        atomicAdd(&g_deg[edge_at(ei, NE + e, is64)], 1);
    gridbar(&gen);

    // P2: per-block inclusive scan -> exclusive offsets + block totals
    {
        int v = (gid < NN) ? g_deg[gid] : 0;
        s[tid] = v;
        __syncthreads();
        for (int o = 1; o < 1024; o <<= 1) {
            int t = (tid >= o) ? s[tid - o] : 0;
            __syncthreads();
            s[tid] += t;
            __syncthreads();
        }
        if (gid < NN) g_off[gid] = s[tid] - v;
        if (tid == 1023) g_bsum[bid] = s[tid];
    }
    gridbar(&gen);

    // P3: block 0 scans the NB block totals (exclusive)
    if (bid == 0) {
        int v = (tid < NB) ? g_bsum[tid] : 0;
        if (tid < 128) s[tid] = v;
        __syncthreads();
        for (int o = 1; o < 128; o <<= 1) {
            int t = (tid >= o && tid < 128) ? s[tid - o] : 0;
            __syncthreads();
            if (tid < 128) s[tid] += t;
            __syncthreads();
        }
        if (tid < NB) g_bsum[tid] = s[tid] - v;
    }
    gridbar(&gen);

    // P4: add block offsets
    if (gid < NN) g_off[gid] += g_bsum[bid];
    gridbar(&gen);

    // P5: scatter edges into CSR
    for (int e = gid; e < NE; e += NB * 1024) {
        int d = edge_at(ei, NE + e, is64);
        int pos = g_off[d] + atomicAdd(&g_cur[d], 1);
        g_csr[pos] = edge_at(ei, e, is64);
    }
}

// ---------------- mean aggregation: one warp per node, float4 lanes ----------------
__global__ void k_agg(const float* __restrict__ X, float* __restrict__ out) {
    int warp = (blockIdx.x * blockDim.x + threadIdx.x) >> 5;
    if (warp >= NN) return;
    int lane = threadIdx.x & 31;
    int beg = g_off[warp];
    int d = g_deg[warp];
    const float4* Xv = (const float4*)X;
    float4 acc = make_float4(0.f, 0.f, 0.f, 0.f);
    int j = 0;
    for (; j + 1 < d; j += 2) {   // 2-way MLP
        int s0 = __ldg(&g_csr[beg + j]);
        int s1 = __ldg(&g_csr[beg + j + 1]);
        float4 v0 = __ldg(&Xv[(size_t)s0 * 32 + lane]);
        float4 v1 = __ldg(&Xv[(size_t)s1 * 32 + lane]);
        acc.x += v0.x + v1.x; acc.y += v0.y + v1.y;
        acc.z += v0.z + v1.z; acc.w += v0.w + v1.w;
    }
    if (j < d) {
        int s0 = __ldg(&g_csr[beg + j]);
        float4 v0 = __ldg(&Xv[(size_t)s0 * 32 + lane]);
        acc.x += v0.x; acc.y += v0.y; acc.z += v0.z; acc.w += v0.w;
    }
    float inv = (d > 0) ? (1.0f / (float)d) : 0.0f;
    acc.x *= inv; acc.y *= inv; acc.z *= inv; acc.w *= inv;
    ((float4*)out)[(size_t)warp * 32 + lane] = acc;
}

// ---------------- tf32 tensor-core fused dual GEMM (double-buffered) ----------------
// C[i][o] = sum_{k<256} Acat[i][k] * Wcat[k][o] + bias[o]  (opt ReLU)
//   Acat[i][k] = k<128 ? A1[i][k] : A2[i][k-128]
// Block 128x128, 8 warps (4x2), warp tile 32x64 = 2x8 m16n8k8 frags, BK=16.
__device__ __forceinline__ unsigned f2tf(float f) {
    unsigned u;
    asm("cvt.rna.tf32.f32 %0, %1;" : "=r"(u) : "f"(f));
    return u;
}

__global__ __launch_bounds__(256, 2)
void k_gemm(const float* __restrict__ A1, const float* __restrict__ A2,
            const float* __restrict__ W, const float* __restrict__ bias,
            float* __restrict__ C, int n, int doRelu)
{
    __shared__ unsigned As[2][128][20];   // [buf][row][k]  pad 20 -> conflict-free frags
    __shared__ unsigned Bs[2][16][136];   // [buf][k][col]  pad 136 -> conflict-free frags

    const int tid  = threadIdx.x;
    const int lane = tid & 31;
    const int warp = tid >> 5;
    const int warpM = warp & 3;        // 4 warp-rows of 32
    const int warpN = warp >> 2;       // 2 warp-cols of 64
    const int rowBase = warpM * 32;
    const int colBase = warpN * 64;
    const int row0 = blockIdx.x * 128;

    const int qid = lane >> 2;         // 0..7
    const int rid = lane & 3;          // 0..3

    float c[2][8][4];
#pragma unroll
    for (int mi = 0; mi < 2; mi++)
#pragma unroll
        for (int ni = 0; ni < 8; ni++)
#pragma unroll
            for (int t = 0; t < 4; t++) c[mi][ni][t] = 0.f;

    const int aRow = tid >> 1;             // 0..127
    const int aK   = (tid & 1) * 8;        // 0 or 8
    const int bK   = tid >> 4;             // 0..15
    const int bCol = (tid & 15) * 8;       // 0..120
    const int r = row0 + aRow;
    const bool rOK = (r < n);

    float ar[8], br[8];

    // G2R for tile 0
    {
        const float* p = A1 + (size_t)r * DD + aK;
        float4 a0 = make_float4(0.f, 0.f, 0.f, 0.f), a1 = a0;
        if (rOK) { a0 = *(const float4*)p; a1 = *(const float4*)(p + 4); }
        ar[0] = a0.x; ar[1] = a0.y; ar[2] = a0.z; ar[3] = a0.w;
        ar[4] = a1.x; ar[5] = a1.y; ar[6] = a1.z; ar[7] = a1.w;
        const float* bp = W + bK * DD + bCol;
        float4 b0 = *(const float4*)bp;
        float4 b1 = *(const float4*)(bp + 4);
        br[0] = b0.x; br[1] = b0.y; br[2] = b0.z; br[3] = b0.w;
        br[4] = b1.x; br[5] = b1.y; br[6] = b1.z; br[7] = b1.w;
    }
    // R2S into buf 0
    {
        uint4 u;
        u.x = f2tf(ar[0]); u.y = f2tf(ar[1]); u.z = f2tf(ar[2]); u.w = f2tf(ar[3]);
        *(uint4*)&As[0][aRow][aK] = u;
        u.x = f2tf(ar[4]); u.y = f2tf(ar[5]); u.z = f2tf(ar[6]); u.w = f2tf(ar[7]);
        *(uint4*)&As[0][aRow][aK + 4] = u;
        u.x = f2tf(br[0]); u.y = f2tf(br[1]); u.z = f2tf(br[2]); u.w = f2tf(br[3]);
        *(uint4*)&Bs[0][bK][bCol] = u;
        u.x = f2tf(br[4]); u.y = f2tf(br[5]); u.z = f2tf(br[6]); u.w = f2tf(br[7]);
        *(uint4*)&Bs[0][bK][bCol + 4] = u;
    }
    __syncthreads();

#pragma unroll
    for (int it = 0; it < 16; it++) {
        // prefetch next tile into registers (latency overlapped with MMA below)
        if (it < 15) {
            const int k0 = (it + 1) * 16;
            const float* Asrc = (k0 < 128) ? A1 : A2;
            const float* p = Asrc + (size_t)r * DD + (k0 & 127) + aK;
            float4 a0 = make_float4(0.f, 0.f, 0.f, 0.f), a1 = a0;
            if (rOK) { a0 = *(const float4*)p; a1 = *(const float4*)(p + 4); }
            ar[0] = a0.x; ar[1] = a0.y; ar[2] = a0.z; ar[3] = a0.w;
            ar[4] = a1.x; ar[5] = a1.y; ar[6] = a1.z; ar[7] = a1.w;
            const float* bp = W + (k0 + bK) * DD + bCol;
            float4 b0 = *(const float4*)bp;
            float4 b1 = *(const float4*)(bp + 4);
            br[0] = b0.x; br[1] = b0.y; br[2] = b0.z; br[3] = b0.w;
            br[4] = b1.x; br[5] = b1.y; br[6] = b1.z; br[7] = b1.w;
        }

        const int buf = it & 1;
#pragma unroll
        for (int kk = 0; kk < 16; kk += 8) {
            unsigned af[2][4];
#pragma unroll
            for (int mi = 0; mi < 2; mi++) {
                const int rr = rowBase + mi * 16 + qid;
                const int kc = kk + rid;
                af[mi][0] = As[buf][rr][kc];
                af[mi][1] = As[buf][rr + 8][kc];
                af[mi][2] = As[buf][rr][kc + 4];
                af[mi][3] = As[buf][rr + 8][kc + 4];
            }
#pragma unroll
            for (int ni = 0; ni < 8; ni++) {
                const int col = colBase + ni * 8 + qid;
                const unsigned bf0 = Bs[buf][kk + rid][col];
                const unsigned bf1 = Bs[buf][kk + 4 + rid][col];
#pragma unroll
                for (int mi = 0; mi < 2; mi++) {
                    asm volatile(
                        "mma.sync.aligned.m16n8k8.row.col.f32.tf32.tf32.f32 "
                        "{%0,%1,%2,%3}, {%4,%5,%6,%7}, {%8,%9}, {%0,%1,%2,%3};\n"
                        : "+f"(c[mi][ni][0]), "+f"(c[mi][ni][1]),
                          "+f"(c[mi][ni][2]), "+f"(c[mi][ni][3])
                        : "r"(af[mi][0]), "r"(af[mi][1]),
                          "r"(af[mi][2]), "r"(af[mi][3]),
                          "r"(bf0), "r"(bf1));
                }
            }
        }

        if (it < 15) {
            const int nbuf = buf ^ 1;
            uint4 u;
            u.x = f2tf(ar[0]); u.y = f2tf(ar[1]); u.z = f2tf(ar[2]); u.w = f2tf(ar[3]);
            *(uint4*)&As[nbuf][aRow][aK] = u;
            u.x = f2tf(ar[4]); u.y = f2tf(ar[5]); u.z = f2tf(ar[6]); u.w = f2tf(ar[7]);
            *(uint4*)&As[nbuf][aRow][aK + 4] = u;
            u.x = f2tf(br[0]); u.y = f2tf(br[1]); u.z = f2tf(br[2]); u.w = f2tf(br[3]);
            *(uint4*)&Bs[nbuf][bK][bCol] = u;
            u.x = f2tf(br[4]); u.y = f2tf(br[5]); u.z = f2tf(br[6]); u.w = f2tf(br[7]);
            *(uint4*)&Bs[nbuf][bK][bCol + 4] = u;
            __syncthreads();
        }
    }

    // epilogue: c0/c1 -> (row, col..col+1), c2/c3 -> (row+8, col..col+1)
#pragma unroll
    for (int mi = 0; mi < 2; mi++) {
#pragma unroll
        for (int ni = 0; ni < 8; ni++) {
            const int col = colBase + ni * 8 + 2 * rid;
            const float bv0 = __ldg(&bias[col]);
            const float bv1 = __ldg(&bias[col + 1]);
            const int rr0 = row0 + rowBase + mi * 16 + qid;
            if (rr0 < n) {
                float v0 = c[mi][ni][0] + bv0;
                float v1 = c[mi][ni][1] + bv1;
                if (doRelu) { v0 = fmaxf(v0, 0.f); v1 = fmaxf(v1, 0.f); }
                *(float2*)&C[(size_t)rr0 * DD + col] = make_float2(v0, v1);
            }
            const int rr1 = rr0 + 8;
            if (rr1 < n) {
                float v2 = c[mi][ni][2] + bv0;
                float v3 = c[mi][ni][3] + bv1;
                if (doRelu) { v2 = fmaxf(v2, 0.f); v3 = fmaxf(v3, 0.f); }
                *(float2*)&C[(size_t)rr1 * DD + col] = make_float2(v2, v3);
            }
        }
    }
}

// ---------------- launch ----------------
extern "C" void kernel_launch(void* const* d_in, const int* in_sizes, int n_in,
                              void* d_out, int out_size) {
    const float* x   = (const float*)d_in[0];
    const void*  ei  = d_in[1];                 // int32 or int64, detected on device
    const float* W1l = (const float*)d_in[2];
    const float* b1  = (const float*)d_in[3];
    const float* W1r = (const float*)d_in[4];
    const float* W2l = (const float*)d_in[5];
    const float* b2  = (const float*)d_in[6];
    const float* W2r = (const float*)d_in[7];
    float* out = (float*)d_out;

    void* p;
    cudaGetSymbolAddress(&p, g_agg);   float* agg = (float*)p;
    cudaGetSymbolAddress(&p, g_h);     float* h   = (float*)p;
    cudaGetSymbolAddress(&p, g_wcat1); float* wc1 = (float*)p;
    cudaGetSymbolAddress(&p, g_wcat2); float* wc2 = (float*)p;

    // launch #0: dtype detect + barrier reset; #1: fused CSR build + wcat
    k_detect<<<1, 32>>>((const int*)ei);
    k_csr<<<NB, 1024>>>(ei, W1l, W1r, W2l, W2r);

    // Layer 1   (#2 agg, #3 gemm — #3 lands in the ncu window)
    k_agg<<<(NN + 7) / 8, 256>>>(x, agg);
    k_gemm<<<(NN + 127) / 128, 256>>>(agg, x, wc1, b1, h, NN, 1);

    // Layer 2
    k_agg<<<(NN + 7) / 8, 256>>>(h, agg);
    k_gemm<<<(NN + 127) / 128, 256>>>(agg, h, wc2, b2, out, NN, 0);
}